// round 2
// baseline (speedup 1.0000x reference)
#include <cuda_runtime.h>
#include <math.h>

#define SQRT2F 1.41421356237309515f
#define INV_SQRT2F 0.70710678118654752f

// ---------------- scratch (static device globals; no allocation) ----------------
__device__ float g_y  [8u*256u*64u*64u];     // conv1 output (lrelu'd)          33.5 MB
__device__ float g_up [8u*256u*128u*128u];   // upsampled conv1 output          134 MB
__device__ float g_upx[8u*256u*128u*128u];   // upsampled x (skip path)         134 MB
__device__ float g_wT1[256*9*256];           // w1 transposed [ci][tap][co] * scale
__device__ float g_wT2[256*9*128];           // w2 transposed [ci][tap][co] * scale
__device__ float g_wskT[256*128];            // w_skip transposed [ci][co] * scale

// ---------------- weight prep: transpose + fold equalized-lr scale ----------------
__global__ void prep_weights(const float* __restrict__ w1,
                             const float* __restrict__ w2,
                             const float* __restrict__ wsk) {
    int i = blockIdx.x * 256 + threadIdx.x;
    const float s3 = 1.0f / 48.0f;   // 1/sqrt(256*9)
    const float s1 = 0.0625f;        // 1/sqrt(256)
    if (i < 256 * 256 * 9) {
        int co  = i / (256 * 9);
        int rem = i % (256 * 9);
        int ci  = rem / 9;
        int tap = rem % 9;
        g_wT1[(ci * 9 + tap) * 256 + co] = w1[i] * s3;
    }
    if (i < 128 * 256 * 9) {
        int co  = i / (256 * 9);
        int rem = i % (256 * 9);
        int ci  = rem / 9;
        int tap = rem % 9;
        g_wT2[(ci * 9 + tap) * 128 + co] = w2[i] * s3;
    }
    if (i < 128 * 256) {
        int co = i / 256;
        int ci = i % 256;
        g_wskT[ci * 128 + co] = wsk[i] * s1;
    }
}

// ---------------- conv3x3 pad=1 + bias + FusedLeakyReLU ----------------
// Block tile: 64 output channels x (8 rows x 16 cols) spatial.
// Thread tile: 8 co x 4 cols (256 threads: co_t=tid&7, sp_t=tid>>3; row=sp_t>>2, cg=sp_t&3)
template<int CIN, int COUT, int H, int W>
__global__ __launch_bounds__(256)
void conv3x3_lrelu(const float* __restrict__ in, const float* __restrict__ wT,
                   const float* __restrict__ bias, float* __restrict__ out) {
    constexpr int TW = 16, TH = 8, CB = 8, BCO = 64;
    __shared__ float s_in[CB][TH + 2][TW + 2];   // 8*10*18 = 1440 fl
    __shared__ float s_w[CB][9][BCO];            // 8*9*64  = 4608 fl

    const int tid  = threadIdx.x;
    const int co_t = tid & 7;
    const int sp_t = tid >> 3;
    const int row  = sp_t >> 2;   // 0..7
    const int cg   = sp_t & 3;    // 0..3 (col group of 4)

    const int tiles_w = W / TW;
    const int n   = blockIdx.z;
    const int co0 = blockIdx.y * BCO;
    const int h0  = (blockIdx.x / tiles_w) * TH;
    const int w0  = (blockIdx.x % tiles_w) * TW;

    float acc[8][4];
    #pragma unroll
    for (int o = 0; o < 8; o++)
        #pragma unroll
        for (int s = 0; s < 4; s++) acc[o][s] = 0.0f;

    const float* in_n = in + (size_t)n * CIN * H * W;

    for (int c0 = 0; c0 < CIN; c0 += CB) {
        // stage input tile (with halo + zero pad)
        for (int i = tid; i < CB * (TH + 2) * (TW + 2); i += 256) {
            int ci  = i / ((TH + 2) * (TW + 2));
            int rem = i % ((TH + 2) * (TW + 2));
            int r = rem / (TW + 2);
            int c = rem % (TW + 2);
            int h = h0 + r - 1, w = w0 + c - 1;
            float v = 0.0f;
            if (h >= 0 && h < H && w >= 0 && w < W)
                v = in_n[((size_t)(c0 + ci) * H + h) * W + w];
            s_in[ci][r][c] = v;
        }
        // stage weights (coalesced: inner index is co)
        for (int i = tid; i < CB * 9 * BCO; i += 256) {
            int ci  = i / (9 * BCO);
            int rem = i % (9 * BCO);
            ((float*)s_w)[i] =
                wT[(size_t)(c0 + ci) * 9 * COUT + (rem / BCO) * COUT + co0 + (rem % BCO)];
        }
        __syncthreads();

        #pragma unroll
        for (int ci = 0; ci < CB; ci++) {
            float iv[3][6];
            #pragma unroll
            for (int ky = 0; ky < 3; ky++)
                #pragma unroll
                for (int c = 0; c < 6; c++)
                    iv[ky][c] = s_in[ci][row + ky][cg * 4 + c];

            #pragma unroll
            for (int ky = 0; ky < 3; ky++)
                #pragma unroll
                for (int kx = 0; kx < 3; kx++) {
                    float wv[8];
                    #pragma unroll
                    for (int o = 0; o < 8; o++) wv[o] = s_w[ci][ky * 3 + kx][o * 8 + co_t];
                    #pragma unroll
                    for (int o = 0; o < 8; o++)
                        #pragma unroll
                        for (int s = 0; s < 4; s++)
                            acc[o][s] = fmaf(wv[o], iv[ky][kx + s], acc[o][s]);
                }
        }
        __syncthreads();
    }

    // epilogue: bias + leaky relu * sqrt(2), vectorized store
    #pragma unroll
    for (int o = 0; o < 8; o++) {
        int co = co0 + o * 8 + co_t;
        float b = bias[co];
        float4 v;
        float* vp = (float*)&v;
        #pragma unroll
        for (int s = 0; s < 4; s++) {
            float y = acc[o][s] + b;
            y = (y >= 0.0f ? y : 0.2f * y) * SQRT2F;
            vp[s] = y;
        }
        *(float4*)&out[(((size_t)n * COUT + co) * H + (h0 + row)) * W + w0 + cg * 4] = v;
    }
}

// ---------------- bilinear 2x upsample (half-pixel, edge-clamped) ----------------
// matches jax.image.resize(..., 'bilinear') / torch align_corners=False for scale 2:
//   out[2m]   = 0.25*y[m-1] + 0.75*y[m]   (m-1 clamped)
//   out[2m+1] = 0.75*y[m]   + 0.25*y[m+1] (m+1 clamped)
template<int HI>
__global__ __launch_bounds__(256)
void upsample2x(const float* __restrict__ in, float* __restrict__ out) {
    constexpr int HO = 2 * HI;
    size_t idx = (size_t)blockIdx.x * 256 + threadIdx.x;
    int ow = (int)(idx & (HO - 1));
    int oh = (int)((idx >> 7) & (HO - 1));     // HO = 128 -> shift 7
    size_t nc = idx >> 14;                     // / (128*128)

    int mh = oh >> 1;
    int h0, h1; float fh0, fh1;
    if (oh & 1) { h0 = mh; h1 = (mh + 1 < HI) ? mh + 1 : HI - 1; fh0 = 0.75f; fh1 = 0.25f; }
    else        { h0 = (mh > 0) ? mh - 1 : 0; h1 = mh;           fh0 = 0.25f; fh1 = 0.75f; }

    int mw = ow >> 1;
    int w0, w1; float fw0, fw1;
    if (ow & 1) { w0 = mw; w1 = (mw + 1 < HI) ? mw + 1 : HI - 1; fw0 = 0.75f; fw1 = 0.25f; }
    else        { w0 = (mw > 0) ? mw - 1 : 0; w1 = mw;           fw0 = 0.25f; fw1 = 0.75f; }

    const float* p = in + nc * HI * HI;
    float v = fh0 * (fw0 * p[h0 * HI + w0] + fw1 * p[h0 * HI + w1])
            + fh1 * (fw0 * p[h1 * HI + w0] + fw1 * p[h1 * HI + w1]);
    out[idx] = v;
}

// ---------------- skip 1x1 conv + final combine: out = (out + skip)/sqrt(2) ----------------
// Block: 128 co (all) x 64 spatial; thread: 8 co x 4 sp (co_t=tid&15, sp_t=tid>>4)
__global__ __launch_bounds__(256)
void skip_combine(const float* __restrict__ upx, const float* __restrict__ wT,
                  float* __restrict__ out) {
    constexpr int CB = 8, HW = 128 * 128, CIN = 256, COUT = 128, SP = 64;
    __shared__ float s_x[CB][SP];
    __shared__ float s_w[CB][COUT];

    const int tid  = threadIdx.x;
    const int co_t = tid & 15;
    const int sp_t = tid >> 4;
    const int n    = blockIdx.z;
    const int p0   = blockIdx.x * SP;

    float acc[8][4];
    #pragma unroll
    for (int o = 0; o < 8; o++)
        #pragma unroll
        for (int s = 0; s < 4; s++) acc[o][s] = 0.0f;

    const float* xn = upx + (size_t)n * CIN * HW;

    for (int c0 = 0; c0 < CIN; c0 += CB) {
        for (int i = tid; i < CB * SP; i += 256) {
            int ci = i / SP, p = i % SP;
            s_x[ci][p] = xn[(size_t)(c0 + ci) * HW + p0 + p];
        }
        for (int i = tid; i < CB * COUT; i += 256) {
            int ci = i / COUT, co = i % COUT;
            s_w[ci][co] = wT[(c0 + ci) * COUT + co];
        }
        __syncthreads();
        #pragma unroll
        for (int ci = 0; ci < CB; ci++) {
            float xv[4];
            #pragma unroll
            for (int s = 0; s < 4; s++) xv[s] = s_x[ci][sp_t * 4 + s];
            #pragma unroll
            for (int o = 0; o < 8; o++) {
                float wv = s_w[ci][o * 16 + co_t];
                #pragma unroll
                for (int s = 0; s < 4; s++) acc[o][s] = fmaf(wv, xv[s], acc[o][s]);
            }
        }
        __syncthreads();
    }

    #pragma unroll
    for (int o = 0; o < 8; o++) {
        int co = o * 16 + co_t;
        size_t base = ((size_t)n * COUT + co) * HW + p0 + sp_t * 4;
        float4 prev = *(const float4*)&out[base];
        float4 v;
        v.x = (prev.x + acc[o][0]) * INV_SQRT2F;
        v.y = (prev.y + acc[o][1]) * INV_SQRT2F;
        v.z = (prev.z + acc[o][2]) * INV_SQRT2F;
        v.w = (prev.w + acc[o][3]) * INV_SQRT2F;
        *(float4*)&out[base] = v;
    }
}

// ---------------- launch ----------------
extern "C" void kernel_launch(void* const* d_in, const int* in_sizes, int n_in,
                              void* d_out, int out_size) {
    const float* x   = (const float*)d_in[0];
    const float* w1  = (const float*)d_in[1];
    const float* b1  = (const float*)d_in[2];
    const float* w2  = (const float*)d_in[3];
    const float* b2  = (const float*)d_in[4];
    const float* wsk = (const float*)d_in[5];
    float* out = (float*)d_out;

    float *p_y, *p_up, *p_upx, *p_wT1, *p_wT2, *p_wskT;
    cudaGetSymbolAddress((void**)&p_y,    g_y);
    cudaGetSymbolAddress((void**)&p_up,   g_up);
    cudaGetSymbolAddress((void**)&p_upx,  g_upx);
    cudaGetSymbolAddress((void**)&p_wT1,  g_wT1);
    cudaGetSymbolAddress((void**)&p_wT2,  g_wT2);
    cudaGetSymbolAddress((void**)&p_wskT, g_wskT);

    // 0) weight transpose + scale fold
    prep_weights<<<(256 * 256 * 9 + 255) / 256, 256>>>(w1, w2, wsk);

    // 1) conv1 (256->256, 64x64) + lrelu -> g_y
    conv3x3_lrelu<256, 256, 64, 64><<<dim3(32, 4, 8), 256>>>(x, p_wT1, b1, p_y);

    // 2) bilinear up x2 of conv1 output -> g_up  (8*256*128*128 elements)
    upsample2x<64><<<(8u * 256u * 128u * 128u) / 256u, 256>>>(p_y, p_up);

    // 3) conv2 (256->128, 128x128) + lrelu -> d_out
    conv3x3_lrelu<256, 128, 128, 128><<<dim3(128, 2, 8), 256>>>(p_up, p_wT2, b2, out);

    // 4) bilinear up x2 of x -> g_upx
    upsample2x<64><<<(8u * 256u * 128u * 128u) / 256u, 256>>>(x, p_upx);

    // 5) skip 1x1 conv + combine into d_out
    skip_combine<<<dim3(16384 / 64, 1, 8), 256>>>(p_upx, p_wskT, out);
}

// round 4
// speedup vs baseline: 3.0679x; 3.0679x over previous
#include <cuda_runtime.h>
#include <cstdint>

#define SQRT2F 1.41421356237309515f
#define INV_SQRT2F 0.70710678118654752f

// ---------------- scratch (static device globals; no allocation) ----------------
__device__ float g_y  [8u*256u*64u*64u];     // conv1 output (lrelu'd)
__device__ float g_up [8u*256u*128u*128u];   // upsampled conv1 output
__device__ float g_upx[8u*256u*128u*128u];   // upsampled x (skip path)
__device__ float g_wB1[72u*256u*32u];        // conv1 B chunks [chunk][co][32 slot-permuted]
__device__ float g_wB2[80u*128u*32u];        // conv2+skip B chunks

// ---------------- helpers ----------------
__device__ __forceinline__ float rna_tf32(float x) {
    uint32_t r;
    asm("cvt.rna.tf32.f32 %0, %1;" : "=r"(r) : "f"(x));
    return __uint_as_float(r);
}
__device__ __forceinline__ void mma16888(float* c, const uint32_t* a, const uint32_t* b) {
    asm volatile(
        "mma.sync.aligned.m16n8k8.row.col.f32.tf32.tf32.f32 "
        "{%0,%1,%2,%3}, {%4,%5,%6,%7}, {%8,%9}, {%0,%1,%2,%3};"
        : "+f"(c[0]), "+f"(c[1]), "+f"(c[2]), "+f"(c[3])
        : "r"(a[0]), "r"(a[1]), "r"(a[2]), "r"(a[3]), "r"(b[0]), "r"(b[1]));
}

// ---------------- weight prep: scale fold + rna(tf32) + slot permutation ----------------
// chunk = cb*9 + tap (conv), then (conv2) 8 skip chunks. Within chunk: [co][32] where
// kk -> offset (kk>>3)*8 + 2*(kk&3) + ((kk&7)>>2)   (pairs (t,t+4) adjacent)
__global__ void prep_w(const float* __restrict__ w1, const float* __restrict__ w2,
                       const float* __restrict__ wsk) {
    int e = blockIdx.x * 256 + threadIdx.x;
    const float s3 = 1.0f / 48.0f;   // 1/sqrt(256*9)
    const float s1 = 0.0625f;        // 1/sqrt(256)
    if (e < 72 * 256 * 32) {
        int i   = e >> 13;           // chunk
        int rem = e & 8191;
        int co  = rem >> 5;
        int kk  = rem & 31;
        int cb = i / 9, tap = i % 9;
        int ci = cb * 32 + kk;
        float v = w1[((size_t)co * 256 + ci) * 9 + tap] * s3;
        int k8 = kk & 7;
        int off = co * 32 + (kk >> 3) * 8 + 2 * (k8 & 3) + (k8 >> 2);
        g_wB1[(size_t)i * 8192 + off] = rna_tf32(v);
    }
    if (e < 80 * 128 * 32) {
        int i   = e >> 12;           // chunk
        int rem = e & 4095;
        int co  = rem >> 5;
        int kk  = rem & 31;
        float v;
        if (i < 72) {
            int cb = i / 9, tap = i % 9;
            v = w2[((size_t)co * 256 + (cb * 32 + kk)) * 9 + tap] * s3;
        } else {
            v = wsk[(size_t)co * 256 + ((i - 72) * 32 + kk)] * s1;
        }
        int k8 = kk & 7;
        int off = co * 32 + (kk >> 3) * 8 + 2 * (k8 & 3) + (k8 >> 2);
        g_wB2[(size_t)i * 4096 + off] = rna_tf32(v);
    }
}

// ---------------- bilinear 2x upsample (half-pixel, edge-clamped) — validated ----------------
template<int HI>
__global__ __launch_bounds__(256)
void upsample2x(const float* __restrict__ in, float* __restrict__ out) {
    size_t idx = (size_t)blockIdx.x * 256 + threadIdx.x;
    int ow = (int)(idx & 127);
    int oh = (int)((idx >> 7) & 127);
    size_t nc = idx >> 14;

    int mh = oh >> 1;
    int h0, h1; float fh0, fh1;
    if (oh & 1) { h0 = mh; h1 = (mh + 1 < HI) ? mh + 1 : HI - 1; fh0 = 0.75f; fh1 = 0.25f; }
    else        { h0 = (mh > 0) ? mh - 1 : 0; h1 = mh;           fh0 = 0.25f; fh1 = 0.75f; }

    int mw = ow >> 1;
    int w0, w1; float fw0, fw1;
    if (ow & 1) { w0 = mw; w1 = (mw + 1 < HI) ? mw + 1 : HI - 1; fw0 = 0.75f; fw1 = 0.25f; }
    else        { w0 = (mw > 0) ? mw - 1 : 0; w1 = mw;           fw0 = 0.25f; fw1 = 0.75f; }

    const float* p = in + nc * HI * HI;
    out[idx] = fh0 * (fw0 * p[h0 * HI + w0] + fw1 * p[h0 * HI + w1])
             + fh1 * (fw0 * p[h1 * HI + w0] + fw1 * p[h1 * HI + w1]);
}

// ---------------- tf32 mma.sync implicit-GEMM conv3x3 (+fused 1x1 skip for conv2) ----------------
// CTA: M=128 pixels x N=128 co. Warps 4(M) x 2(N); warp tile 32x64.
// smem: A [128 m][40] (k pair-interleaved slots), B [128 co][40]. Row stride 40 floats.
template<bool CONV1>
__global__ __launch_bounds__(256, 1)
void conv_mma(const float* __restrict__ in, const float* __restrict__ skipin,
              const float* __restrict__ wB, const float* __restrict__ bias,
              float* __restrict__ out)
{
    constexpr int COUT_TOT = CONV1 ? 256 : 128;
    constexpr int H = CONV1 ? 64 : 128;
    constexpr int W = H;
    constexpr int HW = H * W;
    constexpr int NC = CONV1 ? 72 : 80;

    __shared__ float sA[128 * 40];
    __shared__ float sB[128 * 40];

    const int tid  = threadIdx.x;
    const int lane = tid & 31;
    const int wid  = tid >> 5;
    const int g    = lane >> 2;      // 0..7
    const int t    = lane & 3;       // 0..3
    const int mwarp = wid & 3;
    const int nwarp = wid >> 2;
    const int mbase = mwarp * 32;
    const int Nb    = nwarp * 64;
    const int n   = blockIdx.z;
    const int h0  = CONV1 ? (blockIdx.x * 2) : blockIdx.x;
    const int co0 = CONV1 ? (blockIdx.y * 128) : 0;

    float acc[2][8][4];
    #pragma unroll
    for (int mt = 0; mt < 2; mt++)
        #pragma unroll
        for (int nt = 0; nt < 8; nt++)
            #pragma unroll
            for (int i = 0; i < 4; i++) acc[mt][nt][i] = 0.0f;

    // per-thread bias pair per ntile (cols 2t, 2t+1 of each n8 tile)
    float2 bfr[8];
    #pragma unroll
    for (int nt = 0; nt < 8; nt++) {
        int col = co0 + Nb + nt * 8 + 2 * t;
        bfr[nt] = make_float2(bias[col], bias[col + 1]);
    }

    // staging registers
    float2 ar[8];
    float4 br[4];
    const int sm = tid & 127;                 // this thread's A pixel
    const int sh = CONV1 ? (h0 + (sm >> 6)) : h0;
    const int sw = CONV1 ? (sm & 63) : sm;

    // ---- LDG a chunk into registers ----
    auto ldg_chunk = [&](int c) {
        const bool isskip = (!CONV1) && (c >= 72);
        int c0, ky, kx; const float* src;
        if (isskip) { c0 = (c - 72) * 32; ky = 1; kx = 1; src = skipin; }
        else { c0 = (c / 9) * 32; int tap = c % 9; ky = tap / 3; kx = tap % 3; src = in; }
        const int hh = sh + ky - 1, ww = sw + kx - 1;
        const bool ok = (hh >= 0 && hh < H && ww >= 0 && ww < W);
        const float* base = src + ((size_t)n * 256 + c0) * HW + hh * W + ww;
        #pragma unroll
        for (int j = 0; j < 8; j++) {
            int p = ((tid + j * 256) >> 7);   // 0..15
            int grp = p >> 2, tt = p & 3;
            int k0 = grp * 8 + tt;
            float v0 = 0.f, v1 = 0.f;
            if (ok) {
                v0 = base[(size_t)k0 * HW];
                v1 = base[(size_t)(k0 + 4) * HW];
            }
            ar[j] = make_float2(rna_tf32(v0), rna_tf32(v1));
        }
        const float4* wp = (const float4*)(wB + (size_t)c * (COUT_TOT * 32) + (size_t)co0 * 32);
        #pragma unroll
        for (int j = 0; j < 4; j++) br[j] = wp[tid + j * 256];
    };
    // ---- STS registers into smem ----
    auto sts_chunk = [&]() {
        #pragma unroll
        for (int j = 0; j < 8; j++) {
            int p = ((tid + j * 256) >> 7);
            int grp = p >> 2, tt = p & 3;
            *(float2*)&sA[sm * 40 + grp * 8 + 2 * tt] = ar[j];
        }
        #pragma unroll
        for (int j = 0; j < 4; j++) {
            int f = tid + j * 256;
            int co = f >> 3, q = f & 7;
            *(float4*)&sB[co * 40 + q * 4] = br[j];
        }
    };

    ldg_chunk(0);
    sts_chunk();
    __syncthreads();

    for (int cc = 0; cc < NC; cc++) {
        if (cc + 1 < NC) ldg_chunk(cc + 1);   // prefetch into regs; mma hides latency

        #pragma unroll
        for (int ks = 0; ks < 4; ks++) {
            uint32_t a[2][4];
            uint32_t b[8][2];
            #pragma unroll
            for (int mt = 0; mt < 2; mt++) {
                int r0 = mbase + mt * 16 + g;
                float2 lo = *(const float2*)&sA[r0 * 40 + ks * 8 + 2 * t];
                float2 hi = *(const float2*)&sA[(r0 + 8) * 40 + ks * 8 + 2 * t];
                a[mt][0] = __float_as_uint(lo.x);
                a[mt][2] = __float_as_uint(lo.y);
                a[mt][1] = __float_as_uint(hi.x);
                a[mt][3] = __float_as_uint(hi.y);
            }
            #pragma unroll
            for (int nt = 0; nt < 8; nt++) {
                int nr = Nb + nt * 8 + g;
                float2 bb = *(const float2*)&sB[nr * 40 + ks * 8 + 2 * t];
                b[nt][0] = __float_as_uint(bb.x);
                b[nt][1] = __float_as_uint(bb.y);
            }
            #pragma unroll
            for (int mt = 0; mt < 2; mt++)
                #pragma unroll
                for (int nt = 0; nt < 8; nt++)
                    mma16888(acc[mt][nt], a[mt], b[nt]);
        }

        // after main 72 chunks (conv2): transform acc in-register, then skip chunks add on top
        if (!CONV1 && cc == 71) {
            #pragma unroll
            for (int mt = 0; mt < 2; mt++)
                #pragma unroll
                for (int nt = 0; nt < 8; nt++)
                    #pragma unroll
                    for (int i = 0; i < 4; i++) {
                        float y = acc[mt][nt][i] + ((i & 1) ? bfr[nt].y : bfr[nt].x);
                        acc[mt][nt][i] = (y >= 0.f ? y : 0.2f * y) * SQRT2F;
                    }
        }

        __syncthreads();
        if (cc + 1 < NC) {
            sts_chunk();
            __syncthreads();
        }
    }

    // ---- epilogue ----
    #pragma unroll
    for (int mt = 0; mt < 2; mt++)
        #pragma unroll
        for (int nt = 0; nt < 8; nt++)
            #pragma unroll
            for (int i = 0; i < 4; i++) {
                int m   = mbase + mt * 16 + g + ((i >> 1) << 3);
                int col = co0 + Nb + nt * 8 + 2 * t + (i & 1);
                int h = CONV1 ? (h0 + (m >> 6)) : h0;
                int w = CONV1 ? (m & 63) : m;
                size_t addr = ((size_t)n * COUT_TOT + col) * HW + (size_t)h * W + w;
                if (CONV1) {
                    float y = acc[mt][nt][i] + ((i & 1) ? bfr[nt].y : bfr[nt].x);
                    out[addr] = (y >= 0.f ? y : 0.2f * y) * SQRT2F;
                } else {
                    out[addr] = acc[mt][nt][i] * INV_SQRT2F;
                }
            }
}

// ---------------- launch ----------------
extern "C" void kernel_launch(void* const* d_in, const int* in_sizes, int n_in,
                              void* d_out, int out_size) {
    const float* x   = (const float*)d_in[0];
    const float* w1  = (const float*)d_in[1];
    const float* b1  = (const float*)d_in[2];
    const float* w2  = (const float*)d_in[3];
    const float* b2  = (const float*)d_in[4];
    const float* wsk = (const float*)d_in[5];
    float* out = (float*)d_out;

    float *p_y, *p_up, *p_upx, *p_wB1, *p_wB2;
    cudaGetSymbolAddress((void**)&p_y,   g_y);
    cudaGetSymbolAddress((void**)&p_up,  g_up);
    cudaGetSymbolAddress((void**)&p_upx, g_upx);
    cudaGetSymbolAddress((void**)&p_wB1, g_wB1);
    cudaGetSymbolAddress((void**)&p_wB2, g_wB2);

    // 0) weight prep (scale + rna(tf32) + slot permutation)
    prep_w<<<2304, 256>>>(w1, w2, wsk);

    // 1) conv1 (256->256, 64x64) + lrelu -> g_y    [M: 2 rows x 64, N: 2 halves]
    conv_mma<true><<<dim3(32, 2, 8), 256>>>(x, nullptr, p_wB1, b1, p_y);

    // 2) upsample conv1 output -> g_up ; upsample x -> g_upx
    upsample2x<64><<<(8u * 256u * 128u * 128u) / 256u, 256>>>(p_y, p_up);
    upsample2x<64><<<(8u * 256u * 128u * 128u) / 256u, 256>>>(x, p_upx);

    // 3) conv2 (256->128, 128x128) + lrelu + fused skip -> d_out
    conv_mma<false><<<dim3(128, 1, 8), 256>>>(p_up, p_upx, p_wB2, b2, out);
}